// round 15
// baseline (speedup 1.0000x reference)
#include <cuda_runtime.h>
#include <cuda_fp16.h>

#define NMAX 100000
#define EMAXN 1600000
#define SCB 512

// ---- scratch (device globals). 16B-aligned ----
__device__ __align__(16) __half g_xwh[NMAX * 32];   // f16 rel-projection (gather payload)
__device__ __align__(16) float g_xroot[NMAX * 32];  // fp32 root-projection
__device__ __align__(16) float g_sum1[NMAX * 32];
__device__ __align__(16) float g_hr[NMAX * 8];      // h@W_rel2 (pad 8)
__device__ __align__(16) float g_hroot[NMAX * 8];   // h@W_root2 (pad 8)
__device__ __align__(16) float g_sum2[NMAX * 8];
__device__ __align__(16) int4  g_sdw[EMAXN];        // (src, dst, w-bits, 0)
__device__ __align__(16) int2  g_esw[EMAXN];        // CSR payload: (src, w-bits) sorted by dst
__device__ int g_deg[NMAX];
__device__ int g_rs[NMAX];                          // CSR row starts (exclusive)
__device__ int g_cur[NMAX];
__device__ int g_bs[1024];
__device__ int g_bso[1024];
__device__ int g_is64;

// ---- helpers ----
__device__ __forceinline__ void ffma2(unsigned long long& d, unsigned long long a, unsigned long long b) {
    asm("fma.rn.f32x2 %0, %1, %2, %0;" : "+l"(d) : "l"(a), "l"(b));
}
__device__ __forceinline__ unsigned long long dup2(float a) {
    unsigned long long r;
    asm("mov.b64 %0, {%1, %1};" : "=l"(r) : "f"(a));
    return r;
}
__device__ __forceinline__ float2 u2f2(unsigned long long u) {
    float2 f;
    asm("mov.b64 {%0, %1}, %2;" : "=f"(f.x), "=f"(f.y) : "l"(u));
    return f;
}

// ---- K0: zero deg/cur + sniff int64 vs int32 layout ----
__global__ void k_zc(const int* __restrict__ ei, int N) {
    if (blockIdx.x == 0 && threadIdx.x == 0) {
        int nz = 0;
        #pragma unroll 4
        for (int i = 1; i < 256; i += 2) nz |= ei[i];
        g_is64 = (nz == 0);
    }
    int i = blockIdx.x * blockDim.x + threadIdx.x;
    if (i < N) { g_deg[i] = 0; g_cur[i] = 0; }
}

// ---- unpack indices + degree histogram ----
__global__ void __launch_bounds__(256) k_unpack(const int* __restrict__ ei,
                                                const float* __restrict__ ew,
                                                int E, int N) {
    int e = blockIdx.x * 256 + threadIdx.x;
    if (e >= E) return;
    int s, d;
    if (g_is64) { s = ei[2 * e];  d = ei[2 * E + 2 * e]; }
    else        { s = ei[e];      d = ei[E + e]; }
    if (s < 0 || s >= N) s = 0;
    if (d < 0 || d >= N) d = 0;
    g_sdw[e] = make_int4(s, d, __float_as_int(ew[e]), 0);
    atomicAdd(&g_deg[d], 1);
}

// ---- scan: per-block inclusive ----
__global__ void __launch_bounds__(SCB) k_scan1(int N) {
    __shared__ int s[SCB];
    int t = threadIdx.x;
    int i = blockIdx.x * SCB + t;
    int v = (i < N) ? g_deg[i] : 0;
    s[t] = v;
    __syncthreads();
    #pragma unroll
    for (int off = 1; off < SCB; off <<= 1) {
        int add = (t >= off) ? s[t - off] : 0;
        __syncthreads();
        s[t] += add;
        __syncthreads();
    }
    if (i < N) g_rs[i] = s[t];
    if (t == SCB - 1) g_bs[blockIdx.x] = s[t];
}
// ---- scan: block totals (exclusive) ----
__global__ void __launch_bounds__(SCB) k_scan2(int nb) {
    __shared__ int s[SCB];
    int t = threadIdx.x;
    int v = (t < nb) ? g_bs[t] : 0;
    s[t] = v;
    __syncthreads();
    #pragma unroll
    for (int off = 1; off < SCB; off <<= 1) {
        int add = (t >= off) ? s[t - off] : 0;
        __syncthreads();
        s[t] += add;
        __syncthreads();
    }
    g_bso[t] = s[t] - v;
}
// ---- scan: finalize exclusive row starts ----
__global__ void __launch_bounds__(256) k_scan3(int N) {
    int i = blockIdx.x * 256 + threadIdx.x;
    if (i < N) g_rs[i] = g_rs[i] - g_deg[i] + g_bso[i / SCB];
}
// ---- scatter edges into CSR order ----
__global__ void __launch_bounds__(256) k_scatter(int E) {
    int e = blockIdx.x * 256 + threadIdx.x;
    if (e >= E) return;
    int4 sdw = g_sdw[e];
    int pos = g_rs[sdw.y] + atomicAdd(&g_cur[sdw.y], 1);
    g_esw[pos] = make_int2(sdw.x, sdw.z);
}

// ---- K1: fused projection. rel -> f16 g_xwh, root -> fp32 g_xroot (R12-proven body) ----
#define XPITCH 68
__global__ void __launch_bounds__(128, 4) k_gemm1(
    const float* __restrict__ x,
    const float* __restrict__ Wrel,
    const float* __restrict__ Wroot,
    int N)
{
    extern __shared__ float sm[];
    float* Ws = sm;              // [64 k][64 c]
    float* Xs = sm + 4096;       // [128 node][68]

    const int t  = threadIdx.x;
    const int tx = t & 7;
    const int ty = t >> 3;
    const int n0 = blockIdx.x * 128;

    unsigned long long acc[8][4];
    #pragma unroll
    for (int i = 0; i < 8; i++)
        #pragma unroll
        for (int j = 0; j < 4; j++) acc[i][j] = 0ull;

    for (int kc = 0; kc < 128; kc += 64) {
        #pragma unroll
        for (int i = t; i < 4096; i += 128) {
            int kk = i >> 6, col = i & 63;
            Ws[i] = (col < 32) ? Wrel[(kc + kk) * 32 + col]
                               : Wroot[(kc + kk) * 32 + (col - 32)];
        }
        #pragma unroll
        for (int j = 0; j < 16; j++) {
            int idx  = t + 128 * j;
            int kq   = idx & 15;
            int node = idx >> 4;
            int gn   = n0 + node;
            float4 v = (gn < N) ? *(const float4*)&x[gn * 128 + kc + kq * 4]
                                : make_float4(0.f, 0.f, 0.f, 0.f);
            *(float4*)&Xs[node * XPITCH + kq * 4] = v;
        }
        __syncthreads();

        #pragma unroll 2
        for (int kk = 0; kk < 64; kk += 2) {
            ulonglong2 a0 = *(const ulonglong2*)&Ws[kk * 64 + tx * 4];
            ulonglong2 a1 = *(const ulonglong2*)&Ws[kk * 64 + 32 + tx * 4];
            ulonglong2 b0 = *(const ulonglong2*)&Ws[(kk + 1) * 64 + tx * 4];
            ulonglong2 b1 = *(const ulonglong2*)&Ws[(kk + 1) * 64 + 32 + tx * 4];
            #pragma unroll
            for (int i = 0; i < 8; i++) {
                float2 xp = *(const float2*)&Xs[(ty + 16 * i) * XPITCH + kk];
                unsigned long long ax = dup2(xp.x);
                unsigned long long ay = dup2(xp.y);
                ffma2(acc[i][0], ax, a0.x);
                ffma2(acc[i][1], ax, a0.y);
                ffma2(acc[i][2], ax, a1.x);
                ffma2(acc[i][3], ax, a1.y);
                ffma2(acc[i][0], ay, b0.x);
                ffma2(acc[i][1], ay, b0.y);
                ffma2(acc[i][2], ay, b1.x);
                ffma2(acc[i][3], ay, b1.y);
            }
        }
        __syncthreads();
    }

    #pragma unroll
    for (int i = 0; i < 8; i++) {
        int node = n0 + ty + 16 * i;
        if (node < N) {
            float2 p0 = u2f2(acc[i][0]), p1 = u2f2(acc[i][1]);   // rel
            float2 p2 = u2f2(acc[i][2]), p3 = u2f2(acc[i][3]);   // root
            __half2 h0 = __float22half2_rn(p0);
            __half2 h1 = __float22half2_rn(p1);
            *(uint2*)&g_xwh[node * 32 + tx * 4] =
                make_uint2(*(unsigned*)&h0, *(unsigned*)&h1);
            *(float4*)&g_xroot[node * 32 + tx * 4] = make_float4(p2.x, p2.y, p3.x, p3.y);
        }
    }
}

// ---- edge pass 1 (pull, no atomics): warp per node, 2 edges in flight ----
// half-warp h handles edges beg+2j+h; lane l16 covers cols {2*l16, 2*l16+1}.
__global__ void __launch_bounds__(256) k_edge1_pull(int N) {
    int warp = (blockIdx.x * 256 + threadIdx.x) >> 5;
    int lane = threadIdx.x & 31;
    if (warp >= N) return;
    int node = warp;
    int beg = g_rs[node];
    int deg = g_deg[node];
    int half = lane >> 4;
    int l16  = lane & 15;

    float ax = 0.f, ay = 0.f;
    #pragma unroll 4
    for (int j = half; j < deg; j += 2) {
        int2 sw = g_esw[beg + j];                 // 16 lanes same addr
        float w = __int_as_float(sw.y);
        unsigned hv = *(const unsigned*)&g_xwh[sw.x * 32 + l16 * 2];
        float2 f = __half22float2(*(__half2*)&hv);
        ax += w * f.x;
        ay += w * f.y;
    }
    ax += __shfl_xor_sync(0xffffffffu, ax, 16);
    ay += __shfl_xor_sync(0xffffffffu, ay, 16);
    if (half == 0) *(float2*)&g_sum1[node * 32 + l16 * 2] = make_float2(ax, ay);
}

// ---- combine layer 1 + project layer 2 ----
__global__ void __launch_bounds__(256) k_comb1(
    const float* __restrict__ b1,
    const float* __restrict__ Wrel2,    // [32][5]
    const float* __restrict__ Wroot2,   // [32][5]
    int N)
{
    __shared__ float sW[352];
    int t = threadIdx.x;
    for (int i = t; i < 352; i += 256) {
        sW[i] = (i < 160) ? Wrel2[i]
              : (i < 320) ? Wroot2[i - 160]
                          : b1[i - 320];
    }
    __syncthreads();

    int node = blockIdx.x * 256 + t;
    if (node >= N) return;

    float inv = 1.0f / fmaxf((float)g_deg[node], 1.0f);
    const float4* sp = (const float4*)&g_sum1[node * 32];
    const float4* rp = (const float4*)&g_xroot[node * 32];

    float h[32];
    #pragma unroll
    for (int q = 0; q < 8; q++) {
        float4 s4 = sp[q];
        float4 r4 = rp[q];
        h[4 * q + 0] = fmaxf(s4.x * inv + r4.x + sW[320 + 4 * q + 0], 0.f);
        h[4 * q + 1] = fmaxf(s4.y * inv + r4.y + sW[320 + 4 * q + 1], 0.f);
        h[4 * q + 2] = fmaxf(s4.z * inv + r4.z + sW[320 + 4 * q + 2], 0.f);
        h[4 * q + 3] = fmaxf(s4.w * inv + r4.w + sW[320 + 4 * q + 3], 0.f);
    }

    float hr[5] = {0.f, 0.f, 0.f, 0.f, 0.f};
    float ho[5] = {0.f, 0.f, 0.f, 0.f, 0.f};
    #pragma unroll
    for (int j = 0; j < 32; j++) {
        float hv = h[j];
        #pragma unroll
        for (int c = 0; c < 5; c++) {
            hr[c] += hv * sW[j * 5 + c];
            ho[c] += hv * sW[160 + j * 5 + c];
        }
    }
    *(float4*)&g_hr[node * 8 + 0]    = make_float4(hr[0], hr[1], hr[2], hr[3]);
    *(float4*)&g_hr[node * 8 + 4]    = make_float4(hr[4], 0.f, 0.f, 0.f);
    *(float4*)&g_hroot[node * 8 + 0] = make_float4(ho[0], ho[1], ho[2], ho[3]);
    *(float4*)&g_hroot[node * 8 + 4] = make_float4(ho[4], 0.f, 0.f, 0.f);
}

// ---- edge pass 2 (pull): warp per node, 4 edges in flight x 8 cols ----
__global__ void __launch_bounds__(256) k_edge2_pull(int N) {
    int warp = (blockIdx.x * 256 + threadIdx.x) >> 5;
    int lane = threadIdx.x & 31;
    if (warp >= N) return;
    int node = warp;
    int beg = g_rs[node];
    int deg = g_deg[node];
    int q = lane >> 3;     // edge offset 0..3
    int r = lane & 7;      // col

    float acc = 0.f;
    #pragma unroll 2
    for (int j = q; j < deg; j += 4) {
        int2 sw = g_esw[beg + j];                 // 8 lanes same addr
        acc += g_hr[sw.x * 8 + r];
    }
    acc += __shfl_xor_sync(0xffffffffu, acc, 8);
    acc += __shfl_xor_sync(0xffffffffu, acc, 16);
    if (q == 0) g_sum2[node * 8 + r] = acc;
}

// ---- combine layer 2 + log_softmax ----
__global__ void __launch_bounds__(256) k_final(
    const float* __restrict__ b2,
    float* __restrict__ out,
    int N)
{
    int node = blockIdx.x * 256 + threadIdx.x;
    if (node >= N) return;
    float inv = 1.0f / fmaxf((float)g_deg[node], 1.0f);
    float v[5];
    #pragma unroll
    for (int c = 0; c < 5; c++)
        v[c] = g_sum2[node * 8 + c] * inv + g_hroot[node * 8 + c] + b2[c];

    float m = v[0];
    #pragma unroll
    for (int c = 1; c < 5; c++) m = fmaxf(m, v[c]);
    float sum = 0.f;
    #pragma unroll
    for (int c = 0; c < 5; c++) sum += expf(v[c] - m);
    float lse = m + logf(sum);
    #pragma unroll
    for (int c = 0; c < 5; c++) out[node * 5 + c] = v[c] - lse;
}

extern "C" void kernel_launch(void* const* d_in, const int* in_sizes, int n_in,
                              void* d_out, int out_size)
{
    const float* x      = (const float*)d_in[0];
    const int*   ei     = (const int*)d_in[1];
    const float* ew     = (const float*)d_in[2];
    const float* Wrel1  = (const float*)d_in[3];
    const float* Wroot1 = (const float*)d_in[4];
    const float* b1     = (const float*)d_in[5];
    const float* Wrel2  = (const float*)d_in[6];
    const float* Wroot2 = (const float*)d_in[7];
    const float* b2     = (const float*)d_in[8];
    float*       out    = (float*)d_out;

    int N  = out_size / 5;
    int E  = in_sizes[1] / 2;
    int nb = (N + SCB - 1) / SCB;

    const int GEMM_SMEM = (4096 + 128 * XPITCH) * 4;   // 51200 B
    cudaFuncSetAttribute(k_gemm1, cudaFuncAttributeMaxDynamicSharedMemorySize, GEMM_SMEM);

    static cudaStream_t s2 = nullptr;
    static cudaEvent_t evFork = nullptr, evJoin = nullptr;
    if (!s2) {
        cudaStreamCreateWithFlags(&s2, cudaStreamNonBlocking);
        cudaEventCreateWithFlags(&evFork, cudaEventDisableTiming);
        cudaEventCreateWithFlags(&evJoin, cudaEventDisableTiming);
    }

    // fork: CSR build chain on s2, gemm1 on main stream; join before edge1
    cudaEventRecord(evFork, 0);
    cudaStreamWaitEvent(s2, evFork, 0);
    k_zc     <<<(N + 255) / 256, 256, 0, s2>>>(ei, N);
    k_unpack <<<(E + 255) / 256, 256, 0, s2>>>(ei, ew, E, N);
    k_scan1  <<<nb, SCB, 0, s2>>>(N);
    k_scan2  <<<1, SCB, 0, s2>>>(nb);
    k_scan3  <<<(N + 255) / 256, 256, 0, s2>>>(N);
    k_scatter<<<(E + 255) / 256, 256, 0, s2>>>(E);
    cudaEventRecord(evJoin, s2);

    k_gemm1  <<<(N + 127) / 128, 128, GEMM_SMEM>>>(x, Wrel1, Wroot1, N);
    cudaStreamWaitEvent(0, evJoin, 0);

    k_edge1_pull<<<(N * 32 + 255) / 256, 256>>>(N);
    k_comb1     <<<(N + 255) / 256, 256>>>(b1, Wrel2, Wroot2, N);
    k_edge2_pull<<<(N * 32 + 255) / 256, 256>>>(N);
    k_final     <<<(N + 255) / 256, 256>>>(b2, out, N);
}